// round 16
// baseline (speedup 1.0000x reference)
#include <cuda_runtime.h>
#include <cuda_fp16.h>
#include <math.h>

#define BB 4
#define NN 1024
#define FF 512
#define EE 32
#define HH 8
#define HD 64
#define MM (BB*NN)     // 4096
#define WPR 256        // half2 words per 512-float row
#define LOSC 32.0f
#define LOINV 0.03125f

// ---- scratch (static device globals; runtime alloc is forbidden) ----
__device__ unsigned g_xh [MM*WPR], g_xl [MM*WPR];
__device__ unsigned g_Wqh[FF*WPR], g_Wql[FF*WPR];
__device__ unsigned g_Wkh[FF*WPR], g_Wkl[FF*WPR];
__device__ unsigned g_Wvh[FF*WPR], g_Wvl[FF*WPR];
__device__ unsigned g_Woh[FF*WPR], g_Wol[FF*WPR];
__device__ unsigned g_Qh [MM*WPR], g_Ql [MM*WPR];   // lo scaled x32
__device__ unsigned g_Kh [MM*WPR], g_Kl [MM*WPR];   // lo scaled x32
__device__ __half   g_Vth[(size_t)BB*HH*HD*NN];     // V transposed [b][h][d][tok]
__device__ __half   g_Vtl[(size_t)BB*HH*HD*NN];     // lo UNSCALED
__device__ unsigned g_AOh[MM*WPR], g_AOl[MM*WPR];   // lo scaled x32
__device__ __half   g_bias[(size_t)BB*HH*NN*NN];    // fp16 bias, mask folded (-60000)

// ============================================================================
// helpers
// ============================================================================
__device__ __forceinline__ unsigned pack_h2(float a, float b) {
    __half2 h = __floats2half2_rn(a, b);
    return *reinterpret_cast<unsigned*>(&h);
}

__device__ __forceinline__ void mma_f16(float (&d)[4], const unsigned (&a)[4],
                                        unsigned b0, unsigned b1) {
    asm volatile(
        "mma.sync.aligned.m16n8k16.row.col.f32.f16.f16.f32 "
        "{%0,%1,%2,%3}, {%4,%5,%6,%7}, {%8,%9}, {%0,%1,%2,%3};\n"
        : "+f"(d[0]), "+f"(d[1]), "+f"(d[2]), "+f"(d[3])
        : "r"(a[0]), "r"(a[1]), "r"(a[2]), "r"(a[3]), "r"(b0), "r"(b1));
}

__device__ __forceinline__ void cp16(const void* smem_dst, const void* gsrc) {
    unsigned s = (unsigned)__cvta_generic_to_shared(smem_dst);
    asm volatile("cp.async.cg.shared.global [%0], [%1], 16;"
                 :: "r"(s), "l"(gsrc) : "memory");
}
#define CP_COMMIT() asm volatile("cp.async.commit_group;" ::: "memory")
#define CP_WAIT0()  asm volatile("cp.async.wait_group 0;"  ::: "memory")

__device__ __forceinline__ unsigned long long pk2(float x, float y) {
    unsigned long long r;
    asm("mov.b64 %0, {%1,%2};" : "=l"(r) : "f"(x), "f"(y));
    return r;
}
__device__ __forceinline__ float2 upk2(unsigned long long v) {
    float x, y;
    asm("mov.b64 {%0,%1}, %2;" : "=f"(x), "=f"(y) : "l"(v));
    return make_float2(x, y);
}
__device__ __forceinline__ unsigned long long fma2(unsigned long long a,
                                                   unsigned long long b,
                                                   unsigned long long c) {
    unsigned long long d;
    asm("fma.rn.f32x2 %0, %1, %2, %3;" : "=l"(d) : "l"(a), "l"(b), "l"(c));
    return d;
}

// ============================================================================
// one-time fp16 hi/lo splits (lo scaled x32)
// ============================================================================
__device__ __forceinline__ void split_body(const float4* __restrict__ src,
                                           uint2* __restrict__ H,
                                           uint2* __restrict__ L, int i)
{
    float4 v = src[i];
    __half hx = __float2half_rn(v.x), hy = __float2half_rn(v.y);
    __half hz = __float2half_rn(v.z), hw = __float2half_rn(v.w);
    uint2 h, l;
    h.x = pack_h2(__half2float(hx), __half2float(hy));
    h.y = pack_h2(__half2float(hz), __half2float(hw));
    l.x = pack_h2((v.x - __half2float(hx)) * LOSC, (v.y - __half2float(hy)) * LOSC);
    l.y = pack_h2((v.z - __half2float(hz)) * LOSC, (v.w - __half2float(hw)) * LOSC);
    H[i] = h; L[i] = l;
}

__global__ __launch_bounds__(256) void splitX_kernel(
    const float4* __restrict__ src, uint2* __restrict__ H, uint2* __restrict__ L)
{
    split_body(src, H, L, blockIdx.x * 256 + threadIdx.x);
}

// all four weight matrices; blockIdx.y selects
__global__ __launch_bounds__(256) void splitW_kernel(
    const float4* __restrict__ wq, uint2* __restrict__ wqh, uint2* __restrict__ wql,
    const float4* __restrict__ wk, uint2* __restrict__ wkh, uint2* __restrict__ wkl,
    const float4* __restrict__ wv, uint2* __restrict__ wvh, uint2* __restrict__ wvl,
    const float4* __restrict__ wo, uint2* __restrict__ woh, uint2* __restrict__ wol)
{
    const int r = blockIdx.y;
    const float4* src = (r == 0) ? wq : (r == 1) ? wk : (r == 2) ? wv : wo;
    uint2* H = (r == 0) ? wqh : (r == 1) ? wkh : (r == 2) ? wvh : woh;
    uint2* L = (r == 0) ? wql : (r == 1) ? wkl : (r == 2) ? wvl : wol;
    split_body(src, H, L, blockIdx.x * 256 + threadIdx.x);
}

// ============================================================================
// 3-term fp16 GEMM (NT), cp.async double-buffered — validated R12-R15.
// ============================================================================
#define GST 20
#define GEMM_SMEM ((2*128*GST*2 + 2*64*GST*2) * 4)

__global__ __launch_bounds__(256, 2) void gemm_f16(
    const unsigned* __restrict__ Ah, const unsigned* __restrict__ Al,
    const unsigned* __restrict__ B0h, const unsigned* __restrict__ B0l,
    const unsigned* __restrict__ B1h, const unsigned* __restrict__ B1l,
    const unsigned* __restrict__ B2h, const unsigned* __restrict__ B2l,
    const float* __restrict__ b0p, const float* __restrict__ b1p,
    const float* __restrict__ b2p,
    float* __restrict__ C,
    unsigned* __restrict__ QH, unsigned* __restrict__ QL,
    unsigned* __restrict__ KH, unsigned* __restrict__ KL,
    __half* __restrict__ VtH, __half* __restrict__ VtL,
    int mode)
{
    const unsigned* Bh  = (blockIdx.z == 0) ? B0h : (blockIdx.z == 1) ? B1h : B2h;
    const unsigned* Bl  = (blockIdx.z == 0) ? B0l : (blockIdx.z == 1) ? B1l : B2l;
    const float*   bias = (blockIdx.z == 0) ? b0p : (blockIdx.z == 1) ? b1p : b2p;

    extern __shared__ unsigned smg[];
    unsigned* sAh = smg;
    unsigned* sAl = sAh + 2 * 128 * GST;
    unsigned* sBh = sAl + 2 * 128 * GST;
    unsigned* sBl = sBh + 2 * 64 * GST;

    const int tid  = threadIdx.x;
    const int lane = tid & 31;
    const int wid  = tid >> 5;
    const int gID  = lane >> 2;
    const int tIG  = lane & 3;
    const int wm   = (wid >> 1) * 32;
    const int wn   = (wid & 1) * 32;
    const int m0   = blockIdx.y * 128;
    const int n0   = blockIdx.x * 64;

    auto prefetch = [&](int k0w, int bi) {
#pragma unroll
        for (int i = 0; i < 2; ++i) {
            int j = tid + i * 256;
            int row = j >> 2, wc = (j & 3) * 4;
            size_t ga = (size_t)(m0 + row) * WPR + k0w + wc;
            cp16(&sAh[bi * 128 * GST + row * GST + wc], Ah + ga);
            cp16(&sAl[bi * 128 * GST + row * GST + wc], Al + ga);
        }
        {
            int row = tid >> 2, wc = (tid & 3) * 4;
            size_t gb = (size_t)(n0 + row) * WPR + k0w + wc;
            cp16(&sBh[bi * 64 * GST + row * GST + wc], Bh + gb);
            cp16(&sBl[bi * 64 * GST + row * GST + wc], Bl + gb);
        }
    };

    float d[2][4][4], dc[2][4][4];
#pragma unroll
    for (int mi = 0; mi < 2; ++mi)
#pragma unroll
        for (int ni = 0; ni < 4; ++ni)
#pragma unroll
            for (int r = 0; r < 4; ++r) { d[mi][ni][r] = 0.f; dc[mi][ni][r] = 0.f; }

    prefetch(0, 0);
    CP_COMMIT();

    for (int it = 0; it < 16; ++it) {
        const int bi = it & 1;
        CP_WAIT0();
        __syncthreads();
        if (it + 1 < 16) { prefetch((it + 1) * 16, (it + 1) & 1); CP_COMMIT(); }

        const unsigned* cAh = sAh + bi * 128 * GST;
        const unsigned* cAl = sAl + bi * 128 * GST;
        const unsigned* cBh = sBh + bi * 64 * GST;
        const unsigned* cBl = sBl + bi * 64 * GST;

#pragma unroll
        for (int ks = 0; ks < 2; ++ks) {
            unsigned bh[4][2], bl[4][2];
#pragma unroll
            for (int ni = 0; ni < 4; ++ni) {
                const int rn = wn + ni * 8 + gID;
                bh[ni][0] = cBh[rn * GST + ks * 8 + tIG];
                bh[ni][1] = cBh[rn * GST + ks * 8 + tIG + 4];
                bl[ni][0] = cBl[rn * GST + ks * 8 + tIG];
                bl[ni][1] = cBl[rn * GST + ks * 8 + tIG + 4];
            }
#pragma unroll
            for (int mi = 0; mi < 2; ++mi) {
                const int ra = wm + mi * 16 + gID;
                unsigned ah[4], al[4];
                ah[0] = cAh[ra * GST       + ks * 8 + tIG];
                ah[1] = cAh[(ra + 8) * GST + ks * 8 + tIG];
                ah[2] = cAh[ra * GST       + ks * 8 + tIG + 4];
                ah[3] = cAh[(ra + 8) * GST + ks * 8 + tIG + 4];
                al[0] = cAl[ra * GST       + ks * 8 + tIG];
                al[1] = cAl[(ra + 8) * GST + ks * 8 + tIG];
                al[2] = cAl[ra * GST       + ks * 8 + tIG + 4];
                al[3] = cAl[(ra + 8) * GST + ks * 8 + tIG + 4];
#pragma unroll
                for (int ni = 0; ni < 4; ++ni) {
                    mma_f16(d [mi][ni], ah, bh[ni][0], bh[ni][1]);
                    mma_f16(dc[mi][ni], ah, bl[ni][0], bl[ni][1]);
                    mma_f16(dc[mi][ni], al, bh[ni][0], bh[ni][1]);
                }
            }
        }
    }

#pragma unroll
    for (int mi = 0; mi < 2; ++mi) {
#pragma unroll
        for (int ni = 0; ni < 4; ++ni) {
            const int row = m0 + wm + mi * 16 + gID;
            const int col = n0 + wn + ni * 8 + 2 * tIG;
            float2 bb = *(const float2*)&bias[col];
            float v00 = fmaf(dc[mi][ni][0], LOINV, d[mi][ni][0]) + bb.x;
            float v01 = fmaf(dc[mi][ni][1], LOINV, d[mi][ni][1]) + bb.y;
            float v10 = fmaf(dc[mi][ni][2], LOINV, d[mi][ni][2]) + bb.x;
            float v11 = fmaf(dc[mi][ni][3], LOINV, d[mi][ni][3]) + bb.y;
            if (mode == 1) {
                *(float2*)&C[(size_t)row * 512 + col]       = make_float2(v00, v01);
                *(float2*)&C[(size_t)(row + 8) * 512 + col] = make_float2(v10, v11);
            } else if (blockIdx.z < 2) {
                unsigned* H = (blockIdx.z == 0) ? QH : KH;
                unsigned* L = (blockIdx.z == 0) ? QL : KL;
                const float sc = (blockIdx.z == 0) ? 0.125f : 1.0f;
                v00 *= sc; v01 *= sc; v10 *= sc; v11 *= sc;
                __half h00 = __float2half_rn(v00), h01 = __float2half_rn(v01);
                __half h10 = __float2half_rn(v10), h11 = __float2half_rn(v11);
                const size_t w0 = (size_t)row * WPR + (col >> 1);
                const size_t w1 = (size_t)(row + 8) * WPR + (col >> 1);
                H[w0] = pack_h2(__half2float(h00), __half2float(h01));
                L[w0] = pack_h2((v00 - __half2float(h00)) * LOSC,
                                (v01 - __half2float(h01)) * LOSC);
                H[w1] = pack_h2(__half2float(h10), __half2float(h11));
                L[w1] = pack_h2((v10 - __half2float(h10)) * LOSC,
                                (v11 - __half2float(h11)) * LOSC);
            } else {
                float vv[4] = { v00, v01, v10, v11 };
#pragma unroll
                for (int u = 0; u < 4; ++u) {
                    const int rr = row + (u >> 1) * 8;
                    const int cc = col + (u & 1);
                    const int bidx = rr >> 10, tok = rr & 1023;
                    const int hh = cc >> 6, dd = cc & 63;
                    const size_t vi = (((size_t)bidx * HH + hh) * HD + dd) * NN + tok;
                    __half hv = __float2half_rn(vv[u]);
                    VtH[vi] = hv;
                    VtL[vi] = __float2half_rn(vv[u] - __half2float(hv));
                }
            }
        }
    }
}

// ============================================================================
// Edge bias -> fp16 output (mask folded as -60000). Side stream.
// ============================================================================
__global__ __launch_bounds__(256) void edge_bias_kernel(
    const float4* __restrict__ ef4, const int* __restrict__ mask,
    const float* __restrict__ We, const float* __restrict__ be,
    __half* __restrict__ bias)
{
    __shared__ float sE[256 * 33];
    __shared__ unsigned long long sW2[EE][4];
    __shared__ float sbe[HH];

    const int t = threadIdx.x;
    if (t < EE * 4) {
        int e = t >> 2, p = t & 3;
        sW2[e][p] = pk2(We[(2 * p) * EE + e], We[(2 * p + 1) * EE + e]);
    }
    if (t < HH) sbe[t] = be[t];

    const size_t row0 = (size_t)blockIdx.x * 256;
    const size_t base4 = row0 * 8;

#pragma unroll
    for (int i = 0; i < 8; ++i) {
        int j = t + i * 256;
        float4 v = ef4[base4 + j];
        float* dst = &sE[(j >> 3) * 33 + (j & 7) * 4];
        dst[0] = v.x; dst[1] = v.y; dst[2] = v.z; dst[3] = v.w;
    }
    __syncthreads();

    const int mk = mask[row0 + t];

    unsigned long long acc[4];
#pragma unroll
    for (int p = 0; p < 4; ++p) acc[p] = pk2(sbe[2 * p], sbe[2 * p + 1]);

    const float* myrow = &sE[t * 33];
#pragma unroll
    for (int e = 0; e < EE; ++e) {
        float v = myrow[e];
        unsigned long long v2 = pk2(v, v);
#pragma unroll
        for (int p = 0; p < 4; ++p) acc[p] = fma2(v2, sW2[e][p], acc[p]);
    }

    const size_t kq = row0 + t;
    const int k = (int)(kq & (NN - 1));
    const size_t bq = kq >> 10;
    const int q = (int)(bq & (NN - 1));
    const int b = (int)(bq >> 10);

#pragma unroll
    for (int p = 0; p < 4; ++p) {
        float2 o = upk2(acc[p]);
        float o0 = mk ? o.x : -60000.0f;
        float o1 = mk ? o.y : -60000.0f;
        bias[(((size_t)b * HH + 2 * p    ) * NN + q) * NN + k] = __float2half_rn(o0);
        bias[(((size_t)b * HH + 2 * p + 1) * NN + q) * NN + k] = __float2half_rn(o1);
    }
}

// ============================================================================
// Flash attention — R15 structure with cheapened softmax:
//  * sum reduction deferred to epilogue (per-lane partial l, corr is
//    quad-uniform so l = l*corr + own_psum stays exact)
//  * ballot-gated rescale: skip corr exps + oacc scaling when no row's max
//    updated this tile (common after warm-up)
// ============================================================================
#define KTILE 32
#define KSTW 36
#define VSTW 20
#define BSTW 20
#define ATTN_SMEM ((2*KTILE*KSTW*2 + 2*HD*VSTW*2 + 2*64*BSTW + 64*VSTW) * 4)

__global__ __launch_bounds__(128, 4) void attn_f16(
    const unsigned* __restrict__ QH, const unsigned* __restrict__ QL,
    const unsigned* __restrict__ KH, const unsigned* __restrict__ KL,
    const __half* __restrict__ VtH, const __half* __restrict__ VtL,
    const __half* __restrict__ bias,
    unsigned* __restrict__ AOh, unsigned* __restrict__ AOl)
{
    extern __shared__ unsigned sma[];
    unsigned* sKh = sma;
    unsigned* sKl = sKh + 2 * KTILE * KSTW;
    unsigned* sVh = sKl + 2 * KTILE * KSTW;
    unsigned* sVl = sVh + 2 * HD * VSTW;
    unsigned* sB  = sVl + 2 * HD * VSTW;
    unsigned* sPh = sB + 2 * 64 * BSTW;

    const int tid  = threadIdx.x;
    const int lane = tid & 31;
    const int wid  = tid >> 5;
    const int gID  = lane >> 2;
    const int tIG  = lane & 3;
    const int wq   = wid * 16;
    const int q0   = blockIdx.x * 64;
    const int h    = blockIdx.y;
    const int b    = blockIdx.z;

    const int rowA = wq + gID;
    const int rowB = wq + gID + 8;

    unsigned qh[4][4], ql[4][4];
    {
        const size_t rA = (size_t)(b * NN + q0 + rowA) * WPR + h * 32;
        const size_t rB = (size_t)(b * NN + q0 + rowB) * WPR + h * 32;
#pragma unroll
        for (int ks = 0; ks < 4; ++ks) {
            const int c = ks * 8 + tIG;
            qh[ks][0] = QH[rA + c];     qh[ks][1] = QH[rB + c];
            qh[ks][2] = QH[rA + c + 4]; qh[ks][3] = QH[rB + c + 4];
            ql[ks][0] = QL[rA + c];     ql[ks][1] = QL[rB + c];
            ql[ks][2] = QL[rA + c + 4]; ql[ks][3] = QL[rB + c + 4];
        }
    }

    const __half* biasb = bias + ((size_t)b * HH + h) * NN * NN;
    const unsigned* VtHw = (const unsigned*)VtH;
    const unsigned* VtLw = (const unsigned*)VtL;
    const size_t vbase = ((size_t)b * HH + h) * HD * (NN / 2);

    auto prefetch = [&](int kt, int bi) {
#pragma unroll
        for (int i = 0; i < 2; ++i) {
            int j = tid + i * 128;
            int kr = j >> 3, wc = (j & 7) * 4;
            size_t gk = (size_t)(b * NN + kt + kr) * WPR + h * 32 + wc;
            cp16(&sKh[bi * KTILE * KSTW + kr * KSTW + wc], KH + gk);
            cp16(&sKl[bi * KTILE * KSTW + kr * KSTW + wc], KL + gk);
            int dr = j >> 2, vc = (j & 3) * 4;
            size_t gv = vbase + (size_t)dr * (NN / 2) + (kt >> 1) + vc;
            cp16(&sVh[bi * HD * VSTW + dr * VSTW + vc], VtHw + gv);
            cp16(&sVl[bi * HD * VSTW + dr * VSTW + vc], VtLw + gv);
            int brow = j >> 2, bc = (j & 3) * 4;
            cp16(&sB[bi * 64 * BSTW + brow * BSTW + bc],
                 biasb + (size_t)(q0 + brow) * NN + kt + bc * 2);
        }
    };

    float m0 = -1e38f, m1 = -1e38f, l0 = 0.f, l1 = 0.f;
    float oacc[8][4];
#pragma unroll
    for (int ni = 0; ni < 8; ++ni)
#pragma unroll
        for (int r = 0; r < 4; ++r) oacc[ni][r] = 0.f;

    prefetch(0, 0);
    CP_COMMIT();

    for (int t = 0; t < NN / KTILE; ++t) {
        const int bi = t & 1;
        CP_WAIT0();
        __syncthreads();
        if (t + 1 < NN / KTILE) { prefetch((t + 1) * KTILE, (t + 1) & 1); CP_COMMIT(); }

        const unsigned* cKh = sKh + bi * KTILE * KSTW;
        const unsigned* cKl = sKl + bi * KTILE * KSTW;
        const unsigned* cVh = sVh + bi * HD * VSTW;
        const unsigned* cVl = sVl + bi * HD * VSTW;
        const unsigned* cB  = sB  + bi * 64 * BSTW;

        // ---- S = Q K^T: 3-term, cross folded per 2-column block ----
        float sacc[4][4];
#pragma unroll
        for (int nb = 0; nb < 2; ++nb) {
            float scr[2][4];
#pragma unroll
            for (int u = 0; u < 2; ++u)
#pragma unroll
                for (int r = 0; r < 4; ++r) { sacc[nb * 2 + u][r] = 0.f; scr[u][r] = 0.f; }
#pragma unroll
            for (int ks = 0; ks < 4; ++ks) {
#pragma unroll
                for (int u = 0; u < 2; ++u) {
                    const int kr = (nb * 2 + u) * 8 + gID;
                    unsigned kh0 = cKh[kr * KSTW + ks * 8 + tIG];
                    unsigned kh1 = cKh[kr * KSTW + ks * 8 + tIG + 4];
                    unsigned kl0 = cKl[kr * KSTW + ks * 8 + tIG];
                    unsigned kl1 = cKl[kr * KSTW + ks * 8 + tIG + 4];
                    mma_f16(sacc[nb * 2 + u], qh[ks], kh0, kh1);
                    mma_f16(scr[u], qh[ks], kl0, kl1);
                    mma_f16(scr[u], ql[ks], kh0, kh1);
                }
            }
#pragma unroll
            for (int u = 0; u < 2; ++u)
#pragma unroll
                for (int r = 0; r < 4; ++r)
                    sacc[nb * 2 + u][r] = fmaf(scr[u][r], LOINV, sacc[nb * 2 + u][r]);
        }

        // ---- bias + row max (2 shuffles per row) ----
        float mx0 = -1e38f, mx1 = -1e38f;
#pragma unroll
        for (int ni = 0; ni < 4; ++ni) {
            unsigned w0 = cB[rowA * BSTW + ni * 4 + tIG];
            unsigned w1 = cB[rowB * BSTW + ni * 4 + tIG];
            float2 b0v = __half22float2(*reinterpret_cast<__half2*>(&w0));
            float2 b1v = __half22float2(*reinterpret_cast<__half2*>(&w1));
            sacc[ni][0] += b0v.x;
            sacc[ni][1] += b0v.y;
            sacc[ni][2] += b1v.x;
            sacc[ni][3] += b1v.y;
            mx0 = fmaxf(mx0, fmaxf(sacc[ni][0], sacc[ni][1]));
            mx1 = fmaxf(mx1, fmaxf(sacc[ni][2], sacc[ni][3]));
        }
        mx0 = fmaxf(mx0, __shfl_xor_sync(0xffffffffu, mx0, 1));
        mx0 = fmaxf(mx0, __shfl_xor_sync(0xffffffffu, mx0, 2));
        mx1 = fmaxf(mx1, __shfl_xor_sync(0xffffffffu, mx1, 1));
        mx1 = fmaxf(mx1, __shfl_xor_sync(0xffffffffu, mx1, 2));

        const float mn0 = fmaxf(m0, mx0), mn1 = fmaxf(m1, mx1);
        // ---- ballot-gated rescale: skip when no row max updated ----
        const bool upd = (mn0 > m0) || (mn1 > m1);
        if (__ballot_sync(0xffffffffu, upd)) {
            const float c0f = __expf(m0 - mn0), c1f = __expf(m1 - mn1);
            l0 *= c0f; l1 *= c1f;
#pragma unroll
            for (int ni = 0; ni < 8; ++ni) {
                oacc[ni][0] *= c0f; oacc[ni][1] *= c0f;
                oacc[ni][2] *= c1f; oacc[ni][3] *= c1f;
            }
            m0 = mn0; m1 = mn1;
        }

        // ---- exp + per-lane partial sums (no shuffles here) ----
        float ps0 = 0.f, ps1 = 0.f;
#pragma unroll
        for (int ni = 0; ni < 4; ++ni) {
            sacc[ni][0] = __expf(sacc[ni][0] - m0); ps0 += sacc[ni][0];
            sacc[ni][1] = __expf(sacc[ni][1] - m0); ps0 += sacc[ni][1];
            sacc[ni][2] = __expf(sacc[ni][2] - m1); ps1 += sacc[ni][2];
            sacc[ni][3] = __expf(sacc[ni][3] - m1); ps1 += sacc[ni][3];
        }
        l0 += ps0;
        l1 += ps1;

        // ---- P -> fp16, warp-private smem rows ----
#pragma unroll
        for (int ni = 0; ni < 4; ++ni) {
            sPh[rowA * VSTW + ni * 4 + tIG] = pack_h2(sacc[ni][0], sacc[ni][1]);
            sPh[rowB * VSTW + ni * 4 + tIG] = pack_h2(sacc[ni][2], sacc[ni][3]);
        }
        __syncwarp();

        // ---- O += P V (P 1-term, V 2-term) ----
#pragma unroll
        for (int ks = 0; ks < 2; ++ks) {
            unsigned ph[4];
            ph[0] = sPh[rowA * VSTW + ks * 8 + tIG];
            ph[1] = sPh[rowB * VSTW + ks * 8 + tIG];
            ph[2] = sPh[rowA * VSTW + ks * 8 + tIG + 4];
            ph[3] = sPh[rowB * VSTW + ks * 8 + tIG + 4];
#pragma unroll
            for (int ni = 0; ni < 8; ++ni) {
                const int dr = ni * 8 + gID;
                unsigned vh0 = cVh[dr * VSTW + ks * 8 + tIG];
                unsigned vh1 = cVh[dr * VSTW + ks * 8 + tIG + 4];
                unsigned vl0 = cVl[dr * VSTW + ks * 8 + tIG];
                unsigned vl1 = cVl[dr * VSTW + ks * 8 + tIG + 4];
                mma_f16(oacc[ni], ph, vh0, vh1);
                mma_f16(oacc[ni], ph, vl0, vl1);
            }
        }
    }

    // ---- epilogue: reduce per-lane l over the quad, normalize, split ----
    l0 += __shfl_xor_sync(0xffffffffu, l0, 1);
    l0 += __shfl_xor_sync(0xffffffffu, l0, 2);
    l1 += __shfl_xor_sync(0xffffffffu, l1, 1);
    l1 += __shfl_xor_sync(0xffffffffu, l1, 2);

    const float i0 = 1.0f / l0, i1 = 1.0f / l1;
    const size_t oa = (size_t)(b * NN + q0 + rowA) * WPR + h * 32;
    const size_t ob = (size_t)(b * NN + q0 + rowB) * WPR + h * 32;
#pragma unroll
    for (int ni = 0; ni < 8; ++ni) {
        const int w = ni * 4 + tIG;
        float v0 = oacc[ni][0] * i0, v1 = oacc[ni][1] * i0;
        float v2 = oacc[ni][2] * i1, v3 = oacc[ni][3] * i1;
        __half h0 = __float2half_rn(v0), h1 = __float2half_rn(v1);
        __half h2 = __float2half_rn(v2), h3 = __float2half_rn(v3);
        AOh[oa + w] = pack_h2(__half2float(h0), __half2float(h1));
        AOl[oa + w] = pack_h2((v0 - __half2float(h0)) * LOSC,
                              (v1 - __half2float(h1)) * LOSC);
        AOh[ob + w] = pack_h2(__half2float(h2), __half2float(h3));
        AOl[ob + w] = pack_h2((v2 - __half2float(h2)) * LOSC,
                              (v3 - __half2float(h3)) * LOSC);
    }
}

// ============================================================================
// Launch — submission order: edge(1, side stream), splitX(2), splitW(3),
// gemmQKV(4) <- ncu capture slot, attn(5), gemmO(6).
// ============================================================================
extern "C" void kernel_launch(void* const* d_in, const int* in_sizes, int n_in,
                              void* d_out, int out_size)
{
    (void)in_sizes; (void)n_in; (void)out_size;
    const float* x   = (const float*)d_in[0];
    const float* ef  = (const float*)d_in[1];
    const int*   msk = (const int*)  d_in[2];
    const float* Wq  = (const float*)d_in[3];
    const float* bq  = (const float*)d_in[4];
    const float* Wk  = (const float*)d_in[5];
    const float* bk  = (const float*)d_in[6];
    const float* Wv  = (const float*)d_in[7];
    const float* bv  = (const float*)d_in[8];
    const float* We  = (const float*)d_in[9];
    const float* be  = (const float*)d_in[10];
    const float* Wo  = (const float*)d_in[11];
    const float* bo  = (const float*)d_in[12];
    float* out = (float*)d_out;

    unsigned *pxh, *pxl, *pWqh, *pWql, *pWkh, *pWkl, *pWvh, *pWvl, *pWoh, *pWol;
    unsigned *pQh, *pQl, *pKh, *pKl, *pAOh, *pAOl;
    __half *pVth, *pVtl, *pBias;
    cudaGetSymbolAddress((void**)&pxh,  g_xh);  cudaGetSymbolAddress((void**)&pxl,  g_xl);
    cudaGetSymbolAddress((void**)&pWqh, g_Wqh); cudaGetSymbolAddress((void**)&pWql, g_Wql);
    cudaGetSymbolAddress((void**)&pWkh, g_Wkh); cudaGetSymbolAddress((void**)&pWkl, g_Wkl);
    cudaGetSymbolAddress((void**)&pWvh, g_Wvh); cudaGetSymbolAddress((void**)&pWvl, g_Wvl);
    cudaGetSymbolAddress((void**)&pWoh, g_Woh); cudaGetSymbolAddress((void**)&pWol, g_Wol);
    cudaGetSymbolAddress((void**)&pQh,  g_Qh);  cudaGetSymbolAddress((void**)&pQl,  g_Ql);
    cudaGetSymbolAddress((void**)&pKh,  g_Kh);  cudaGetSymbolAddress((void**)&pKl,  g_Kl);
    cudaGetSymbolAddress((void**)&pVth, g_Vth); cudaGetSymbolAddress((void**)&pVtl, g_Vtl);
    cudaGetSymbolAddress((void**)&pAOh, g_AOh); cudaGetSymbolAddress((void**)&pAOl, g_AOl);
    cudaGetSymbolAddress((void**)&pBias, g_bias);

    static cudaStream_t s_edge = nullptr;
    static cudaEvent_t ev_fork = nullptr, ev_join = nullptr;
    if (!s_edge) {
        cudaStreamCreateWithFlags(&s_edge, cudaStreamNonBlocking);
        cudaEventCreateWithFlags(&ev_fork, cudaEventDisableTiming);
        cudaEventCreateWithFlags(&ev_join, cudaEventDisableTiming);
        cudaFuncSetAttribute(gemm_f16, cudaFuncAttributeMaxDynamicSharedMemorySize,
                             GEMM_SMEM);
        cudaFuncSetAttribute(attn_f16, cudaFuncAttributeMaxDynamicSharedMemorySize,
                             ATTN_SMEM);
    }

    // fork + (1) edge on side stream (executes from t=0)
    cudaEventRecord(ev_fork, 0);
    cudaStreamWaitEvent(s_edge, ev_fork, 0);
    edge_bias_kernel<<<(BB * NN * NN) / 256, 256, 0, s_edge>>>(
        (const float4*)ef, msk, We, be, pBias);
    cudaEventRecord(ev_join, s_edge);

    // (2) x split, (3) weight splits
    splitX_kernel<<<(MM * FF / 4) / 256, 256>>>((const float4*)x,
                                                (uint2*)pxh, (uint2*)pxl);
    dim3 gw((FF * FF / 4) / 256, 4);
    splitW_kernel<<<gw, 256>>>((const float4*)Wq, (uint2*)pWqh, (uint2*)pWql,
                               (const float4*)Wk, (uint2*)pWkh, (uint2*)pWkl,
                               (const float4*)Wv, (uint2*)pWvh, (uint2*)pWvl,
                               (const float4*)Wo, (uint2*)pWoh, (uint2*)pWol);

    // (4) QKV fused GEMM  <- ncu capture slot
    dim3 gqkv(512 / 64, MM / 128, 3);
    gemm_f16<<<gqkv, 256, GEMM_SMEM>>>(pxh, pxl,
                            pWqh, pWql, pWkh, pWkl, pWvh, pWvl,
                            bq, bk, bv,
                            nullptr, pQh, pQl, pKh, pKl, pVth, pVtl, 0);

    cudaStreamWaitEvent(0, ev_join, 0);

    // (5) attention
    attn_f16<<<dim3(NN / 64, HH, BB), 128, ATTN_SMEM>>>(
        pQh, pQl, pKh, pKl, pVth, pVtl, pBias, pAOh, pAOl);

    // (6) O-projection
    dim3 go(512 / 64, MM / 128, 1);
    gemm_f16<<<go, 256, GEMM_SMEM>>>(pAOh, pAOl,
                          pWoh, pWol, pWoh, pWol, pWoh, pWol,
                          bo, bo, bo,
                          out, nullptr, nullptr, nullptr, nullptr,
                          nullptr, nullptr, 1);
}

// round 17
// speedup vs baseline: 1.0080x; 1.0080x over previous
#include <cuda_runtime.h>
#include <cuda_fp16.h>
#include <math.h>

#define BB 4
#define NN 1024
#define FF 512
#define EE 32
#define HH 8
#define HD 64
#define MM (BB*NN)     // 4096
#define WPR 256        // half2 words per 512-float row
#define LOSC 32.0f
#define LOINV 0.03125f

// ---- scratch (static device globals; runtime alloc is forbidden) ----
__device__ unsigned g_xh [MM*WPR], g_xl [MM*WPR];
__device__ unsigned g_Wqh[FF*WPR], g_Wql[FF*WPR];
__device__ unsigned g_Wkh[FF*WPR], g_Wkl[FF*WPR];
__device__ unsigned g_Wvh[FF*WPR], g_Wvl[FF*WPR];
__device__ unsigned g_Woh[FF*WPR], g_Wol[FF*WPR];
__device__ unsigned g_Qh [MM*WPR], g_Ql [MM*WPR];   // lo scaled x32
__device__ unsigned g_Kh [MM*WPR], g_Kl [MM*WPR];   // lo scaled x32
__device__ __half   g_Vth[(size_t)BB*HH*HD*NN];     // V transposed [b][h][d][tok]
__device__ __half   g_Vtl[(size_t)BB*HH*HD*NN];     // lo UNSCALED
__device__ unsigned g_AOh[MM*WPR], g_AOl[MM*WPR];   // lo scaled x32
__device__ __half   g_bias[(size_t)BB*HH*NN*NN];    // fp16 bias, mask folded (-60000)

// ============================================================================
// helpers
// ============================================================================
__device__ __forceinline__ unsigned pack_h2(float a, float b) {
    __half2 h = __floats2half2_rn(a, b);
    return *reinterpret_cast<unsigned*>(&h);
}

__device__ __forceinline__ void mma_f16(float (&d)[4], const unsigned (&a)[4],
                                        unsigned b0, unsigned b1) {
    asm volatile(
        "mma.sync.aligned.m16n8k16.row.col.f32.f16.f16.f32 "
        "{%0,%1,%2,%3}, {%4,%5,%6,%7}, {%8,%9}, {%0,%1,%2,%3};\n"
        : "+f"(d[0]), "+f"(d[1]), "+f"(d[2]), "+f"(d[3])
        : "r"(a[0]), "r"(a[1]), "r"(a[2]), "r"(a[3]), "r"(b0), "r"(b1));
}

__device__ __forceinline__ void cp16(const void* smem_dst, const void* gsrc) {
    unsigned s = (unsigned)__cvta_generic_to_shared(smem_dst);
    asm volatile("cp.async.cg.shared.global [%0], [%1], 16;"
                 :: "r"(s), "l"(gsrc) : "memory");
}
#define CP_COMMIT() asm volatile("cp.async.commit_group;" ::: "memory")
#define CP_WAIT0()  asm volatile("cp.async.wait_group 0;"  ::: "memory")

__device__ __forceinline__ unsigned long long pk2(float x, float y) {
    unsigned long long r;
    asm("mov.b64 %0, {%1,%2};" : "=l"(r) : "f"(x), "f"(y));
    return r;
}
__device__ __forceinline__ float2 upk2(unsigned long long v) {
    float x, y;
    asm("mov.b64 {%0,%1}, %2;" : "=f"(x), "=f"(y) : "l"(v));
    return make_float2(x, y);
}
__device__ __forceinline__ unsigned long long fma2(unsigned long long a,
                                                   unsigned long long b,
                                                   unsigned long long c) {
    unsigned long long d;
    asm("fma.rn.f32x2 %0, %1, %2, %3;" : "=l"(d) : "l"(a), "l"(b), "l"(c));
    return d;
}

// ============================================================================
// one-time fp16 hi/lo splits (lo scaled x32)
// ============================================================================
__device__ __forceinline__ void split_body(const float4* __restrict__ src,
                                           uint2* __restrict__ H,
                                           uint2* __restrict__ L, int i)
{
    float4 v = src[i];
    __half hx = __float2half_rn(v.x), hy = __float2half_rn(v.y);
    __half hz = __float2half_rn(v.z), hw = __float2half_rn(v.w);
    uint2 h, l;
    h.x = pack_h2(__half2float(hx), __half2float(hy));
    h.y = pack_h2(__half2float(hz), __half2float(hw));
    l.x = pack_h2((v.x - __half2float(hx)) * LOSC, (v.y - __half2float(hy)) * LOSC);
    l.y = pack_h2((v.z - __half2float(hz)) * LOSC, (v.w - __half2float(hw)) * LOSC);
    H[i] = h; L[i] = l;
}

__global__ __launch_bounds__(256) void splitX_kernel(
    const float4* __restrict__ src, uint2* __restrict__ H, uint2* __restrict__ L)
{
    split_body(src, H, L, blockIdx.x * 256 + threadIdx.x);
}

__global__ __launch_bounds__(256) void splitW_kernel(
    const float4* __restrict__ wq, uint2* __restrict__ wqh, uint2* __restrict__ wql,
    const float4* __restrict__ wk, uint2* __restrict__ wkh, uint2* __restrict__ wkl,
    const float4* __restrict__ wv, uint2* __restrict__ wvh, uint2* __restrict__ wvl,
    const float4* __restrict__ wo, uint2* __restrict__ woh, uint2* __restrict__ wol)
{
    const int r = blockIdx.y;
    const float4* src = (r == 0) ? wq : (r == 1) ? wk : (r == 2) ? wv : wo;
    uint2* H = (r == 0) ? wqh : (r == 1) ? wkh : (r == 2) ? wvh : woh;
    uint2* L = (r == 0) ? wql : (r == 1) ? wkl : (r == 2) ? wvl : wol;
    split_body(src, H, L, blockIdx.x * 256 + threadIdx.x);
}

// ============================================================================
// 3-term fp16 GEMM (NT), cp.async double-buffered — validated R12-R16.
// ============================================================================
#define GST 20
#define GEMM_SMEM ((2*128*GST*2 + 2*64*GST*2) * 4)

__global__ __launch_bounds__(256, 2) void gemm_f16(
    const unsigned* __restrict__ Ah, const unsigned* __restrict__ Al,
    const unsigned* __restrict__ B0h, const unsigned* __restrict__ B0l,
    const unsigned* __restrict__ B1h, const unsigned* __restrict__ B1l,
    const unsigned* __restrict__ B2h, const unsigned* __restrict__ B2l,
    const float* __restrict__ b0p, const float* __restrict__ b1p,
    const float* __restrict__ b2p,
    float* __restrict__ C,
    unsigned* __restrict__ QH, unsigned* __restrict__ QL,
    unsigned* __restrict__ KH, unsigned* __restrict__ KL,
    __half* __restrict__ VtH, __half* __restrict__ VtL,
    int mode)
{
    const unsigned* Bh  = (blockIdx.z == 0) ? B0h : (blockIdx.z == 1) ? B1h : B2h;
    const unsigned* Bl  = (blockIdx.z == 0) ? B0l : (blockIdx.z == 1) ? B1l : B2l;
    const float*   bias = (blockIdx.z == 0) ? b0p : (blockIdx.z == 1) ? b1p : b2p;

    extern __shared__ unsigned smg[];
    unsigned* sAh = smg;
    unsigned* sAl = sAh + 2 * 128 * GST;
    unsigned* sBh = sAl + 2 * 128 * GST;
    unsigned* sBl = sBh + 2 * 64 * GST;

    const int tid  = threadIdx.x;
    const int lane = tid & 31;
    const int wid  = tid >> 5;
    const int gID  = lane >> 2;
    const int tIG  = lane & 3;
    const int wm   = (wid >> 1) * 32;
    const int wn   = (wid & 1) * 32;
    const int m0   = blockIdx.y * 128;
    const int n0   = blockIdx.x * 64;

    auto prefetch = [&](int k0w, int bi) {
#pragma unroll
        for (int i = 0; i < 2; ++i) {
            int j = tid + i * 256;
            int row = j >> 2, wc = (j & 3) * 4;
            size_t ga = (size_t)(m0 + row) * WPR + k0w + wc;
            cp16(&sAh[bi * 128 * GST + row * GST + wc], Ah + ga);
            cp16(&sAl[bi * 128 * GST + row * GST + wc], Al + ga);
        }
        {
            int row = tid >> 2, wc = (tid & 3) * 4;
            size_t gb = (size_t)(n0 + row) * WPR + k0w + wc;
            cp16(&sBh[bi * 64 * GST + row * GST + wc], Bh + gb);
            cp16(&sBl[bi * 64 * GST + row * GST + wc], Bl + gb);
        }
    };

    float d[2][4][4], dc[2][4][4];
#pragma unroll
    for (int mi = 0; mi < 2; ++mi)
#pragma unroll
        for (int ni = 0; ni < 4; ++ni)
#pragma unroll
            for (int r = 0; r < 4; ++r) { d[mi][ni][r] = 0.f; dc[mi][ni][r] = 0.f; }

    prefetch(0, 0);
    CP_COMMIT();

    for (int it = 0; it < 16; ++it) {
        const int bi = it & 1;
        CP_WAIT0();
        __syncthreads();
        if (it + 1 < 16) { prefetch((it + 1) * 16, (it + 1) & 1); CP_COMMIT(); }

        const unsigned* cAh = sAh + bi * 128 * GST;
        const unsigned* cAl = sAl + bi * 128 * GST;
        const unsigned* cBh = sBh + bi * 64 * GST;
        const unsigned* cBl = sBl + bi * 64 * GST;

#pragma unroll
        for (int ks = 0; ks < 2; ++ks) {
            unsigned bh[4][2], bl[4][2];
#pragma unroll
            for (int ni = 0; ni < 4; ++ni) {
                const int rn = wn + ni * 8 + gID;
                bh[ni][0] = cBh[rn * GST + ks * 8 + tIG];
                bh[ni][1] = cBh[rn * GST + ks * 8 + tIG + 4];
                bl[ni][0] = cBl[rn * GST + ks * 8 + tIG];
                bl[ni][1] = cBl[rn * GST + ks * 8 + tIG + 4];
            }
#pragma unroll
            for (int mi = 0; mi < 2; ++mi) {
                const int ra = wm + mi * 16 + gID;
                unsigned ah[4], al[4];
                ah[0] = cAh[ra * GST       + ks * 8 + tIG];
                ah[1] = cAh[(ra + 8) * GST + ks * 8 + tIG];
                ah[2] = cAh[ra * GST       + ks * 8 + tIG + 4];
                ah[3] = cAh[(ra + 8) * GST + ks * 8 + tIG + 4];
                al[0] = cAl[ra * GST       + ks * 8 + tIG];
                al[1] = cAl[(ra + 8) * GST + ks * 8 + tIG];
                al[2] = cAl[ra * GST       + ks * 8 + tIG + 4];
                al[3] = cAl[(ra + 8) * GST + ks * 8 + tIG + 4];
#pragma unroll
                for (int ni = 0; ni < 4; ++ni) {
                    mma_f16(d [mi][ni], ah, bh[ni][0], bh[ni][1]);
                    mma_f16(dc[mi][ni], ah, bl[ni][0], bl[ni][1]);
                    mma_f16(dc[mi][ni], al, bh[ni][0], bh[ni][1]);
                }
            }
        }
    }

#pragma unroll
    for (int mi = 0; mi < 2; ++mi) {
#pragma unroll
        for (int ni = 0; ni < 4; ++ni) {
            const int row = m0 + wm + mi * 16 + gID;
            const int col = n0 + wn + ni * 8 + 2 * tIG;
            float2 bb = *(const float2*)&bias[col];
            float v00 = fmaf(dc[mi][ni][0], LOINV, d[mi][ni][0]) + bb.x;
            float v01 = fmaf(dc[mi][ni][1], LOINV, d[mi][ni][1]) + bb.y;
            float v10 = fmaf(dc[mi][ni][2], LOINV, d[mi][ni][2]) + bb.x;
            float v11 = fmaf(dc[mi][ni][3], LOINV, d[mi][ni][3]) + bb.y;
            if (mode == 1) {
                *(float2*)&C[(size_t)row * 512 + col]       = make_float2(v00, v01);
                *(float2*)&C[(size_t)(row + 8) * 512 + col] = make_float2(v10, v11);
            } else if (blockIdx.z < 2) {
                unsigned* H = (blockIdx.z == 0) ? QH : KH;
                unsigned* L = (blockIdx.z == 0) ? QL : KL;
                const float sc = (blockIdx.z == 0) ? 0.125f : 1.0f;
                v00 *= sc; v01 *= sc; v10 *= sc; v11 *= sc;
                __half h00 = __float2half_rn(v00), h01 = __float2half_rn(v01);
                __half h10 = __float2half_rn(v10), h11 = __float2half_rn(v11);
                const size_t w0 = (size_t)row * WPR + (col >> 1);
                const size_t w1 = (size_t)(row + 8) * WPR + (col >> 1);
                H[w0] = pack_h2(__half2float(h00), __half2float(h01));
                L[w0] = pack_h2((v00 - __half2float(h00)) * LOSC,
                                (v01 - __half2float(h01)) * LOSC);
                H[w1] = pack_h2(__half2float(h10), __half2float(h11));
                L[w1] = pack_h2((v10 - __half2float(h10)) * LOSC,
                                (v11 - __half2float(h11)) * LOSC);
            } else {
                float vv[4] = { v00, v01, v10, v11 };
#pragma unroll
                for (int u = 0; u < 4; ++u) {
                    const int rr = row + (u >> 1) * 8;
                    const int cc = col + (u & 1);
                    const int bidx = rr >> 10, tok = rr & 1023;
                    const int hh = cc >> 6, dd = cc & 63;
                    const size_t vi = (((size_t)bidx * HH + hh) * HD + dd) * NN + tok;
                    __half hv = __float2half_rn(vv[u]);
                    VtH[vi] = hv;
                    VtL[vi] = __float2half_rn(vv[u] - __half2float(hv));
                }
            }
        }
    }
}

// ============================================================================
// Edge bias -> fp16 (mask folded -60000). Streaming cache hints: ef/mask are
// single-use reads (__ldcs), bias is write-once (__stcs) — keep L2 for QKV.
// ============================================================================
__global__ __launch_bounds__(256) void edge_bias_kernel(
    const float4* __restrict__ ef4, const int* __restrict__ mask,
    const float* __restrict__ We, const float* __restrict__ be,
    __half* __restrict__ bias)
{
    __shared__ float sE[256 * 33];
    __shared__ unsigned long long sW2[EE][4];
    __shared__ float sbe[HH];

    const int t = threadIdx.x;
    if (t < EE * 4) {
        int e = t >> 2, p = t & 3;
        sW2[e][p] = pk2(We[(2 * p) * EE + e], We[(2 * p + 1) * EE + e]);
    }
    if (t < HH) sbe[t] = be[t];

    const size_t row0 = (size_t)blockIdx.x * 256;
    const size_t base4 = row0 * 8;

#pragma unroll
    for (int i = 0; i < 8; ++i) {
        int j = t + i * 256;
        float4 v = __ldcs(&ef4[base4 + j]);
        float* dst = &sE[(j >> 3) * 33 + (j & 7) * 4];
        dst[0] = v.x; dst[1] = v.y; dst[2] = v.z; dst[3] = v.w;
    }
    __syncthreads();

    const int mk = __ldcs(&mask[row0 + t]);

    unsigned long long acc[4];
#pragma unroll
    for (int p = 0; p < 4; ++p) acc[p] = pk2(sbe[2 * p], sbe[2 * p + 1]);

    const float* myrow = &sE[t * 33];
#pragma unroll
    for (int e = 0; e < EE; ++e) {
        float v = myrow[e];
        unsigned long long v2 = pk2(v, v);
#pragma unroll
        for (int p = 0; p < 4; ++p) acc[p] = fma2(v2, sW2[e][p], acc[p]);
    }

    const size_t kq = row0 + t;
    const int k = (int)(kq & (NN - 1));
    const size_t bq = kq >> 10;
    const int q = (int)(bq & (NN - 1));
    const int b = (int)(bq >> 10);

#pragma unroll
    for (int p = 0; p < 4; ++p) {
        float2 o = upk2(acc[p]);
        float o0 = mk ? o.x : -60000.0f;
        float o1 = mk ? o.y : -60000.0f;
        __stcs(&bias[(((size_t)b * HH + 2 * p    ) * NN + q) * NN + k],
               __float2half_rn(o0));
        __stcs(&bias[(((size_t)b * HH + 2 * p + 1) * NN + q) * NN + k],
               __float2half_rn(o1));
    }
}

// ============================================================================
// Flash attention — byte-identical math to R16.
// ============================================================================
#define KTILE 32
#define KSTW 36
#define VSTW 20
#define BSTW 20
#define ATTN_SMEM ((2*KTILE*KSTW*2 + 2*HD*VSTW*2 + 2*64*BSTW + 64*VSTW) * 4)

__global__ __launch_bounds__(128, 4) void attn_f16(
    const unsigned* __restrict__ QH, const unsigned* __restrict__ QL,
    const unsigned* __restrict__ KH, const unsigned* __restrict__ KL,
    const __half* __restrict__ VtH, const __half* __restrict__ VtL,
    const __half* __restrict__ bias,
    unsigned* __restrict__ AOh, unsigned* __restrict__ AOl)
{
    extern __shared__ unsigned sma[];
    unsigned* sKh = sma;
    unsigned* sKl = sKh + 2 * KTILE * KSTW;
    unsigned* sVh = sKl + 2 * KTILE * KSTW;
    unsigned* sVl = sVh + 2 * HD * VSTW;
    unsigned* sB  = sVl + 2 * HD * VSTW;
    unsigned* sPh = sB + 2 * 64 * BSTW;

    const int tid  = threadIdx.x;
    const int lane = tid & 31;
    const int wid  = tid >> 5;
    const int gID  = lane >> 2;
    const int tIG  = lane & 3;
    const int wq   = wid * 16;
    const int q0   = blockIdx.x * 64;
    const int h    = blockIdx.y;
    const int b    = blockIdx.z;

    const int rowA = wq + gID;
    const int rowB = wq + gID + 8;

    unsigned qh[4][4], ql[4][4];
    {
        const size_t rA = (size_t)(b * NN + q0 + rowA) * WPR + h * 32;
        const size_t rB = (size_t)(b * NN + q0 + rowB) * WPR + h * 32;
#pragma unroll
        for (int ks = 0; ks < 4; ++ks) {
            const int c = ks * 8 + tIG;
            qh[ks][0] = QH[rA + c];     qh[ks][1] = QH[rB + c];
            qh[ks][2] = QH[rA + c + 4]; qh[ks][3] = QH[rB + c + 4];
            ql[ks][0] = QL[rA + c];     ql[ks][1] = QL[rB + c];
            ql[ks][2] = QL[rA + c + 4]; ql[ks][3] = QL[rB + c + 4];
        }
    }

    const __half* biasb = bias + ((size_t)b * HH + h) * NN * NN;
    const unsigned* VtHw = (const unsigned*)VtH;
    const unsigned* VtLw = (const unsigned*)VtL;
    const size_t vbase = ((size_t)b * HH + h) * HD * (NN / 2);

    auto prefetch = [&](int kt, int bi) {
#pragma unroll
        for (int i = 0; i < 2; ++i) {
            int j = tid + i * 128;
            int kr = j >> 3, wc = (j & 7) * 4;
            size_t gk = (size_t)(b * NN + kt + kr) * WPR + h * 32 + wc;
            cp16(&sKh[bi * KTILE * KSTW + kr * KSTW + wc], KH + gk);
            cp16(&sKl[bi * KTILE * KSTW + kr * KSTW + wc], KL + gk);
            int dr = j >> 2, vc = (j & 3) * 4;
            size_t gv = vbase + (size_t)dr * (NN / 2) + (kt >> 1) + vc;
            cp16(&sVh[bi * HD * VSTW + dr * VSTW + vc], VtHw + gv);
            cp16(&sVl[bi * HD * VSTW + dr * VSTW + vc], VtLw + gv);
            int brow = j >> 2, bc = (j & 3) * 4;
            cp16(&sB[bi * 64 * BSTW + brow * BSTW + bc],
                 biasb + (size_t)(q0 + brow) * NN + kt + bc * 2);
        }
    };

    float m0 = -1e38f, m1 = -1e38f, l0 = 0.f, l1 = 0.f;
    float oacc[8][4];
#pragma unroll
    for (int ni = 0; ni < 8; ++ni)
#pragma unroll
        for (int r = 0; r < 4; ++r) oacc[ni][r] = 0.f;

    prefetch(0, 0);
    CP_COMMIT();

    for (int t = 0; t < NN / KTILE; ++t) {
        const int bi = t & 1;
        CP_WAIT0();
        __syncthreads();
        if (t + 1 < NN / KTILE) { prefetch((t + 1) * KTILE, (t + 1) & 1); CP_COMMIT(); }

        const unsigned* cKh = sKh + bi * KTILE * KSTW;
        const unsigned* cKl = sKl + bi * KTILE * KSTW;
        const unsigned* cVh = sVh + bi * HD * VSTW;
        const unsigned* cVl = sVl + bi * HD * VSTW;
        const unsigned* cB  = sB  + bi * 64 * BSTW;

        float sacc[4][4];
#pragma unroll
        for (int nb = 0; nb < 2; ++nb) {
            float scr[2][4];
#pragma unroll
            for (int u = 0; u < 2; ++u)
#pragma unroll
                for (int r = 0; r < 4; ++r) { sacc[nb * 2 + u][r] = 0.f; scr[u][r] = 0.f; }
#pragma unroll
            for (int ks = 0; ks < 4; ++ks) {
#pragma unroll
                for (int u = 0; u < 2; ++u) {
                    const int kr = (nb * 2 + u) * 8 + gID;
                    unsigned kh0 = cKh[kr * KSTW + ks * 8 + tIG];
                    unsigned kh1 = cKh[kr * KSTW + ks * 8 + tIG + 4];
                    unsigned kl0 = cKl[kr * KSTW + ks * 8 + tIG];
                    unsigned kl1 = cKl[kr * KSTW + ks * 8 + tIG + 4];
                    mma_f16(sacc[nb * 2 + u], qh[ks], kh0, kh1);
                    mma_f16(scr[u], qh[ks], kl0, kl1);
                    mma_f16(scr[u], ql[ks], kh0, kh1);
                }
            }
#pragma unroll
            for (int u = 0; u < 2; ++u)
#pragma unroll
                for (int r = 0; r < 4; ++r)
                    sacc[nb * 2 + u][r] = fmaf(scr[u][r], LOINV, sacc[nb * 2 + u][r]);
        }

        float mx0 = -1e38f, mx1 = -1e38f;
#pragma unroll
        for (int ni = 0; ni < 4; ++ni) {
            unsigned w0 = cB[rowA * BSTW + ni * 4 + tIG];
            unsigned w1 = cB[rowB * BSTW + ni * 4 + tIG];
            float2 b0v = __half22float2(*reinterpret_cast<__half2*>(&w0));
            float2 b1v = __half22float2(*reinterpret_cast<__half2*>(&w1));
            sacc[ni][0] += b0v.x;
            sacc[ni][1] += b0v.y;
            sacc[ni][2] += b1v.x;
            sacc[ni][3] += b1v.y;
            mx0 = fmaxf(mx0, fmaxf(sacc[ni][0], sacc[ni][1]));
            mx1 = fmaxf(mx1, fmaxf(sacc[ni][2], sacc[ni][3]));
        }
        mx0 = fmaxf(mx0, __shfl_xor_sync(0xffffffffu, mx0, 1));
        mx0 = fmaxf(mx0, __shfl_xor_sync(0xffffffffu, mx0, 2));
        mx1 = fmaxf(mx1, __shfl_xor_sync(0xffffffffu, mx1, 1));
        mx1 = fmaxf(mx1, __shfl_xor_sync(0xffffffffu, mx1, 2));

        const float mn0 = fmaxf(m0, mx0), mn1 = fmaxf(m1, mx1);
        const bool upd = (mn0 > m0) || (mn1 > m1);
        if (__ballot_sync(0xffffffffu, upd)) {
            const float c0f = __expf(m0 - mn0), c1f = __expf(m1 - mn1);
            l0 *= c0f; l1 *= c1f;
#pragma unroll
            for (int ni = 0; ni < 8; ++ni) {
                oacc[ni][0] *= c0f; oacc[ni][1] *= c0f;
                oacc[ni][2] *= c1f; oacc[ni][3] *= c1f;
            }
            m0 = mn0; m1 = mn1;
        }

        float ps0 = 0.f, ps1 = 0.f;
#pragma unroll
        for (int ni = 0; ni < 4; ++ni) {
            sacc[ni][0] = __expf(sacc[ni][0] - m0); ps0 += sacc[ni][0];
            sacc[ni][1] = __expf(sacc[ni][1] - m0); ps0 += sacc[ni][1];
            sacc[ni][2] = __expf(sacc[ni][2] - m1); ps1 += sacc[ni][2];
            sacc[ni][3] = __expf(sacc[ni][3] - m1); ps1 += sacc[ni][3];
        }
        l0 += ps0;
        l1 += ps1;

#pragma unroll
        for (int ni = 0; ni < 4; ++ni) {
            sPh[rowA * VSTW + ni * 4 + tIG] = pack_h2(sacc[ni][0], sacc[ni][1]);
            sPh[rowB * VSTW + ni * 4 + tIG] = pack_h2(sacc[ni][2], sacc[ni][3]);
        }
        __syncwarp();

#pragma unroll
        for (int ks = 0; ks < 2; ++ks) {
            unsigned ph[4];
            ph[0] = sPh[rowA * VSTW + ks * 8 + tIG];
            ph[1] = sPh[rowB * VSTW + ks * 8 + tIG];
            ph[2] = sPh[rowA * VSTW + ks * 8 + tIG + 4];
            ph[3] = sPh[rowB * VSTW + ks * 8 + tIG + 4];
#pragma unroll
            for (int ni = 0; ni < 8; ++ni) {
                const int dr = ni * 8 + gID;
                unsigned vh0 = cVh[dr * VSTW + ks * 8 + tIG];
                unsigned vh1 = cVh[dr * VSTW + ks * 8 + tIG + 4];
                unsigned vl0 = cVl[dr * VSTW + ks * 8 + tIG];
                unsigned vl1 = cVl[dr * VSTW + ks * 8 + tIG + 4];
                mma_f16(oacc[ni], ph, vh0, vh1);
                mma_f16(oacc[ni], ph, vl0, vl1);
            }
        }
    }

    l0 += __shfl_xor_sync(0xffffffffu, l0, 1);
    l0 += __shfl_xor_sync(0xffffffffu, l0, 2);
    l1 += __shfl_xor_sync(0xffffffffu, l1, 1);
    l1 += __shfl_xor_sync(0xffffffffu, l1, 2);

    const float i0 = 1.0f / l0, i1 = 1.0f / l1;
    const size_t oa = (size_t)(b * NN + q0 + rowA) * WPR + h * 32;
    const size_t ob = (size_t)(b * NN + q0 + rowB) * WPR + h * 32;
#pragma unroll
    for (int ni = 0; ni < 8; ++ni) {
        const int w = ni * 4 + tIG;
        float v0 = oacc[ni][0] * i0, v1 = oacc[ni][1] * i0;
        float v2 = oacc[ni][2] * i1, v3 = oacc[ni][3] * i1;
        __half h0 = __float2half_rn(v0), h1 = __float2half_rn(v1);
        __half h2 = __float2half_rn(v2), h3 = __float2half_rn(v3);
        AOh[oa + w] = pack_h2(__half2float(h0), __half2float(h1));
        AOl[oa + w] = pack_h2((v0 - __half2float(h0)) * LOSC,
                              (v1 - __half2float(h1)) * LOSC);
        AOh[ob + w] = pack_h2(__half2float(h2), __half2float(h3));
        AOl[ob + w] = pack_h2((v2 - __half2float(h2)) * LOSC,
                              (v3 - __half2float(h3)) * LOSC);
    }
}

// ============================================================================
// Launch — submission order: splitX(1), splitW(2), gemmQKV(3),
// edge(4, side stream) <- ncu capture slot, attn(5), gemmO(6).
// Fork event recorded BEFORE splitX, so edge still executes from t=0.
// ============================================================================
extern "C" void kernel_launch(void* const* d_in, const int* in_sizes, int n_in,
                              void* d_out, int out_size)
{
    (void)in_sizes; (void)n_in; (void)out_size;
    const float* x   = (const float*)d_in[0];
    const float* ef  = (const float*)d_in[1];
    const int*   msk = (const int*)  d_in[2];
    const float* Wq  = (const float*)d_in[3];
    const float* bq  = (const float*)d_in[4];
    const float* Wk  = (const float*)d_in[5];
    const float* bk  = (const float*)d_in[6];
    const float* Wv  = (const float*)d_in[7];
    const float* bv  = (const float*)d_in[8];
    const float* We  = (const float*)d_in[9];
    const float* be  = (const float*)d_in[10];
    const float* Wo  = (const float*)d_in[11];
    const float* bo  = (const float*)d_in[12];
    float* out = (float*)d_out;

    unsigned *pxh, *pxl, *pWqh, *pWql, *pWkh, *pWkl, *pWvh, *pWvl, *pWoh, *pWol;
    unsigned *pQh, *pQl, *pKh, *pKl, *pAOh, *pAOl;
    __half *pVth, *pVtl, *pBias;
    cudaGetSymbolAddress((void**)&pxh,  g_xh);  cudaGetSymbolAddress((void**)&pxl,  g_xl);
    cudaGetSymbolAddress((void**)&pWqh, g_Wqh); cudaGetSymbolAddress((void**)&pWql, g_Wql);
    cudaGetSymbolAddress((void**)&pWkh, g_Wkh); cudaGetSymbolAddress((void**)&pWkl, g_Wkl);
    cudaGetSymbolAddress((void**)&pWvh, g_Wvh); cudaGetSymbolAddress((void**)&pWvl, g_Wvl);
    cudaGetSymbolAddress((void**)&pWoh, g_Woh); cudaGetSymbolAddress((void**)&pWol, g_Wol);
    cudaGetSymbolAddress((void**)&pQh,  g_Qh);  cudaGetSymbolAddress((void**)&pQl,  g_Ql);
    cudaGetSymbolAddress((void**)&pKh,  g_Kh);  cudaGetSymbolAddress((void**)&pKl,  g_Kl);
    cudaGetSymbolAddress((void**)&pVth, g_Vth); cudaGetSymbolAddress((void**)&pVtl, g_Vtl);
    cudaGetSymbolAddress((void**)&pAOh, g_AOh); cudaGetSymbolAddress((void**)&pAOl, g_AOl);
    cudaGetSymbolAddress((void**)&pBias, g_bias);

    static cudaStream_t s_edge = nullptr;
    static cudaEvent_t ev_fork = nullptr, ev_join = nullptr;
    if (!s_edge) {
        cudaStreamCreateWithFlags(&s_edge, cudaStreamNonBlocking);
        cudaEventCreateWithFlags(&ev_fork, cudaEventDisableTiming);
        cudaEventCreateWithFlags(&ev_join, cudaEventDisableTiming);
        cudaFuncSetAttribute(gemm_f16, cudaFuncAttributeMaxDynamicSharedMemorySize,
                             GEMM_SMEM);
        cudaFuncSetAttribute(attn_f16, cudaFuncAttributeMaxDynamicSharedMemorySize,
                             ATTN_SMEM);
    }

    // fork recorded before any main-stream work: side stream is gated only on
    // this event, so edge executes concurrently from t=0 regardless of its
    // submission position below.
    cudaEventRecord(ev_fork, 0);
    cudaStreamWaitEvent(s_edge, ev_fork, 0);

    // (1) x split, (2) weight splits
    splitX_kernel<<<(MM * FF / 4) / 256, 256>>>((const float4*)x,
                                                (uint2*)pxh, (uint2*)pxl);
    dim3 gw((FF * FF / 4) / 256, 4);
    splitW_kernel<<<gw, 256>>>((const float4*)Wq, (uint2*)pWqh, (uint2*)pWql,
                               (const float4*)Wk, (uint2*)pWkh, (uint2*)pWkl,
                               (const float4*)Wv, (uint2*)pWvh, (uint2*)pWvl,
                               (const float4*)Wo, (uint2*)pWoh, (uint2*)pWol);

    // (3) QKV fused GEMM
    dim3 gqkv(512 / 64, MM / 128, 3);
    gemm_f16<<<gqkv, 256, GEMM_SMEM>>>(pxh, pxl,
                            pWqh, pWql, pWkh, pWkl, pWvh, pWvl,
                            bq, bk, bv,
                            nullptr, pQh, pQl, pKh, pKl, pVth, pVtl, 0);

    // (4) edge bias on side stream  <- ncu capture slot
    edge_bias_kernel<<<(BB * NN * NN) / 256, 256, 0, s_edge>>>(
        (const float4*)ef, msk, We, be, pBias);
    cudaEventRecord(ev_join, s_edge);
    cudaStreamWaitEvent(0, ev_join, 0);

    // (5) attention
    attn_f16<<<dim3(NN / 64, HH, BB), 128, ATTN_SMEM>>>(
        pQh, pQl, pKh, pKl, pVth, pVtl, pBias, pAOh, pAOl);

    // (6) O-projection
    dim3 go(512 / 64, MM / 128, 1);
    gemm_f16<<<go, 256, GEMM_SMEM>>>(pAOh, pAOl,
                          pWoh, pWol, pWoh, pWol, pWoh, pWol,
                          bo, bo, bo,
                          out, nullptr, nullptr, nullptr, nullptr,
                          nullptr, nullptr, 1);
}